// round 10
// baseline (speedup 1.0000x reference)
#include <cuda_runtime.h>

#define B 256
#define C 50000
#define D 512
#define ALPHA 0.5f

// ---- scan blocks (first in grid) ----
#define OH_SLICES 16
#define NB_OH (B * OH_SLICES)       // 4096
#define OH_ROW4 (C / 4)             // 12500 float4 per row
#define OH_PER_SLICE 782            // 16*782 = 12512 >= 12500
#define SCAN_ITERS 4                // 4*256 >= 782

// ---- copy blocks: 256 thr x 8 float4 = 16 rows of D=512 ----
#define COPY_PER_THREAD 8
#define NB_COPY ((C * D / 4) / (256 * COPY_PER_THREAD))  // 3125, exact

// ---- fixup blocks: LAST in grid, dispatched as copy waves retire ----
#define NB_FIX B                    // 256
#define NB_TOTAL (NB_OH + NB_COPY + NB_FIX)

__device__ int g_labels[B];
__device__ unsigned int g_scan = 0;   // scan completion counter
__device__ unsigned int g_fin  = 0;   // fixup completion counter (for reset)

// (256, 4): allow up to 64 regs so ptxas can front-batch the 7-8 independent
// float4 loads per thread (MLP), instead of staging them at 32 regs.
__global__ void __launch_bounds__(256, 4) center_loss_kernel(
    const float* __restrict__ x,
    const float* __restrict__ onehot,
    const float* __restrict__ centers,
    float* __restrict__ result,
    float* __restrict__ new_centers) {
    int blk = blockIdx.x;
    int tid = threadIdx.x;

    if (blk < NB_OH) {
        // ========== scan: iota-dot; finder block writes label + result =====
        int b = blk >> 4;
        int slice = blk & 15;
        const float4* row = reinterpret_cast<const float4*>(onehot) +
                            (size_t)b * OH_ROW4;
        int lo = slice * OH_PER_SLICE;
        int hi = lo + OH_PER_SLICE;
        if (hi > OH_ROW4) hi = OH_ROW4;

        float acc = 0.0f;
        #pragma unroll
        for (int k = 0; k < SCAN_ITERS; k++) {
            int i = lo + tid + k * 256;
            float4 v = (i < hi) ? row[i] : make_float4(0.f, 0.f, 0.f, 0.f);
            float fi = (float)(4 * i);
            acc += v.x * (fi + 1.0f);
            acc += v.y * (fi + 2.0f);
            acc += v.z * (fi + 3.0f);
            acc += v.w * (fi + 4.0f);
        }

        __shared__ float s_warp[8];
        __shared__ float s_sum;
        #pragma unroll
        for (int off = 16; off > 0; off >>= 1)
            acc += __shfl_down_sync(0xFFFFFFFFu, acc, off);
        if ((tid & 31) == 0) s_warp[tid >> 5] = acc;
        __syncthreads();
        if (tid == 0) {
            float t = 0.0f;
            #pragma unroll
            for (int w = 0; w < 8; w++) t += s_warp[w];
            s_sum = t;
        }
        __syncthreads();

        float s = s_sum;
        if (s > 0.5f) {
            int l = (int)(s + 0.5f) - 1;   // exact: s == label+1 (< 2^24)
            if (tid == 0) g_labels[b] = l;

            // result[b] = ||x[b] - centers[l]||^2
            const float* xb = x + (size_t)b * D;
            const float* cl = centers + (size_t)l * D;
            float r = 0.0f;
            #pragma unroll
            for (int k = 0; k < D / 256; k++) {
                int d = tid + k * 256;
                float df = xb[d] - cl[d];
                r += df * df;
            }
            #pragma unroll
            for (int off = 16; off > 0; off >>= 1)
                r += __shfl_down_sync(0xFFFFFFFFu, r, off);
            if ((tid & 31) == 0) s_warp[tid >> 5] = r;
            __syncthreads();
            if (tid == 0) {
                float t = 0.0f;
                #pragma unroll
                for (int w = 0; w < 8; w++) t += s_warp[w];
                result[b] = t;
            }
        }
        // signal scan completion
        __syncthreads();
        __threadfence();
        if (tid == 0) atomicAdd(&g_scan, 1u);
    } else if (blk < NB_OH + NB_COPY) {
        // ========== pure copy: proven fast path, untouched ================
        int cb = blk - NB_OH;
        const float4* src = reinterpret_cast<const float4*>(centers);
        float4* dst = reinterpret_cast<float4*>(new_centers);
        size_t base = (size_t)cb * (256 * COPY_PER_THREAD) + tid;
        #pragma unroll
        for (int k = 0; k < COPY_PER_THREAD; k++) {
            size_t idx = base + (size_t)k * 256;
            dst[idx] = src[idx];
        }
    } else {
        // ========== fixup: last 256 blocks, dispatched in the final waves ==
        int b = blk - NB_OH - NB_COPY;

        // guard: scan done (expected zero-iteration spin)
        if (tid == 0) {
            while (atomicAdd(&g_scan, 0u) < NB_OH) __nanosleep(64);
        }
        __syncthreads();
        __threadfence();

        __shared__ int s_lab[B];
        __shared__ int s_match[B];
        __shared__ int s_cnt;
        __shared__ int s_first;

        s_lab[tid] = g_labels[tid];
        if (tid == 0) { s_cnt = 0; s_first = B; }
        __syncthreads();

        int l = s_lab[b];
        if (s_lab[tid] == l) {
            int pos = atomicAdd(&s_cnt, 1);
            s_match[pos] = tid;
            atomicMin(&s_first, tid);
        }
        __syncthreads();

        if (b == s_first) {   // lowest-indexed holder rewrites the row
            int n = s_cnt;
            float inv = 1.0f / ((float)n + 1.0f);
            float fn = (float)n;
            #pragma unroll
            for (int k = 0; k < D / 256; k++) {
                int d = tid + k * 256;
                float sx = 0.0f;
                for (int m = 0; m < n; m++)
                    sx += x[(size_t)s_match[m] * D + d];
                float c = centers[(size_t)l * D + d];
                new_centers[(size_t)l * D + d] =
                    c - ALPHA * (fn * c - sx) * inv;
            }
        }

        // retire; last fixup block resets counters (graph replay determinism)
        __syncthreads();
        if (tid == 0) {
            unsigned int f = atomicAdd(&g_fin, 1u);
            if (f == NB_FIX - 1) {
                g_scan = 0;
                g_fin = 0;
                __threadfence();
            }
        }
    }
}

extern "C" void kernel_launch(void* const* d_in, const int* in_sizes, int n_in,
                              void* d_out, int out_size) {
    const float* x       = (const float*)d_in[0];
    const float* onehot  = (const float*)d_in[1];
    const float* centers = (const float*)d_in[2];

    float* result      = (float*)d_out;        // [B, 1]
    float* new_centers = (float*)d_out + B;    // [C, D]

    center_loss_kernel<<<NB_TOTAL, 256>>>(x, onehot, centers,
                                          result, new_centers);
}